// round 8
// baseline (speedup 1.0000x reference)
#include <cuda_runtime.h>
#include <cuda_bf16.h>
#include <cstdint>

#define N_NODES 50000
#define N_EDGES 400000
#define DIM     128
#define GTHREADS 512
#define GBLOCKS  ((N_NODES + 127) / 128)     // 391

#define TSTRIDE 136                          // bf16/row: 272B = 4-bank shift, LDSM conflict-free
#define TILE_ELEMS (128 * TSTRIDE)
#define LO_OFF (TILE_ELEMS * 2)              // byte offset hi-tile -> lo-tile
#define SMEM_SZ (4 * TILE_ELEMS * 2)         // Ah, Al, Bh, Bl  = 139264 B

// ---- scratch (no allocations allowed) ----
__device__ float g_h  [(size_t)N_NODES * DIM];
__device__ float g_agg[(size_t)N_NODES * DIM];
__device__ float g_deg[N_NODES];
__device__ int   g_is64;

// ---------------------------------------------------------------------------
__device__ __forceinline__ uint32_t smem_u32(const void* p) {
    uint32_t a;
    asm("{ .reg .u64 t; cvta.to.shared.u64 t, %1; cvt.u32.u64 %0, t; }"
        : "=r"(a) : "l"(p));
    return a;
}

#define LDSM_X4(r0, r1, r2, r3, a)                                             \
    asm volatile("ldmatrix.sync.aligned.m8n8.x4.shared.b16 {%0,%1,%2,%3}, [%4];" \
                 : "=r"(r0), "=r"(r1), "=r"(r2), "=r"(r3) : "r"(a))

#define MMA_BF16(d, a0, a1, a2, a3, b0, b1)                                    \
    asm volatile("mma.sync.aligned.m16n8k16.row.col.f32.bf16.bf16.f32 "        \
                 "{%0,%1,%2,%3}, {%4,%5,%6,%7}, {%8,%9}, {%0,%1,%2,%3};"       \
                 : "+f"((d).x), "+f"((d).y), "+f"((d).z), "+f"((d).w)          \
                 : "r"(a0), "r"(a1), "r"(a2), "r"(a3), "r"(b0), "r"(b1))

// ---------------------------------------------------------------------------
// detect edge_index dtype (JAX may downcast int64 -> int32)
// ---------------------------------------------------------------------------
__global__ void detect_kernel(const void* eiv) {
    const long long* p = (const long long*)eiv;
    int ok64 = 1;
    for (int i = 0; i < 64; ++i) {
        long long v = p[i];
        if (v < 0 || v >= N_NODES) { ok64 = 0; break; }
    }
    g_is64 = ok64;
}

// ---------------------------------------------------------------------------
// Tensor-core GEMM tile (mma.sync bf16, fp32 acc):
//   Y[128,128] = act( Z[128,128] @ W^T + b )
// fp32 emulated: Z W^T ~= Zh Wh + Zh Wl + Zl Wh  (shared k-step fragments)
// 16 warps in a 4x4 grid; warp = m32 x n32 -> 8 float4 accumulators.
// ---------------------------------------------------------------------------
template<bool FIRST>
__global__ void __launch_bounds__(GTHREADS, 1)
gemm_mma_kernel(const float* __restrict__ Zext,
                const float* __restrict__ W,
                const float* __restrict__ bias,
                float* __restrict__ Yext)
{
    extern __shared__ __align__(16) __nv_bfloat16 smem[];
    __nv_bfloat16* Ah = smem;                       // [+TILE_ELEMS] = Al
    __nv_bfloat16* Bh = smem + 2 * TILE_ELEMS;      // [+TILE_ELEMS] = Bl

    const float* Z = FIRST ? Zext : g_h;
    float*       Y = FIRST ? g_h  : Yext;
    const int tid = threadIdx.x;
    const int row_base = blockIdx.x * 128;

    // ---- fill tiles: thread t -> row r = t>>2, K-quarter kh = (t&3)*32 ----
    {
        const int r  = tid >> 2;
        const int kh = (tid & 3) * 32;

        // B tile: W[c][k], c = r
        const float* wrow = W + r * DIM + kh;
        uint32_t* bh = (uint32_t*)(Bh + r * TSTRIDE + kh);
        uint32_t* bl = (uint32_t*)(Bh + TILE_ELEMS + r * TSTRIDE + kh);
        #pragma unroll 4
        for (int k = 0; k < 32; k += 2) {
            float f0 = wrow[k], f1 = wrow[k + 1];
            __nv_bfloat16 h0 = __float2bfloat16_rn(f0);
            __nv_bfloat16 h1 = __float2bfloat16_rn(f1);
            __nv_bfloat16 l0 = __float2bfloat16_rn(f0 - __bfloat162float(h0));
            __nv_bfloat16 l1 = __float2bfloat16_rn(f1 - __bfloat162float(h1));
            bh[k >> 1] = (uint32_t)__bfloat16_as_ushort(h1) << 16 | __bfloat16_as_ushort(h0);
            bl[k >> 1] = (uint32_t)__bfloat16_as_ushort(l1) << 16 | __bfloat16_as_ushort(l0);
        }

        // A tile: Z row (+ agg/deg residual for second GEMM); OOB rows -> 0
        const int gr = row_base + r;
        uint32_t* ah = (uint32_t*)(Ah + r * TSTRIDE + kh);
        uint32_t* al = (uint32_t*)(Ah + TILE_ELEMS + r * TSTRIDE + kh);
        float inv = 0.f;
        if (!FIRST && gr < N_NODES) inv = 1.0f / fmaxf(g_deg[gr], 1.0f);
        const float* zrow = Z     + (size_t)gr * DIM + kh;
        const float* arow = g_agg + (size_t)gr * DIM + kh;
        #pragma unroll 4
        for (int k = 0; k < 32; k += 2) {
            float f0 = 0.f, f1 = 0.f;
            if (gr < N_NODES) {
                f0 = zrow[k]; f1 = zrow[k + 1];
                if (!FIRST) { f0 += arow[k] * inv; f1 += arow[k + 1] * inv; }
            }
            __nv_bfloat16 h0 = __float2bfloat16_rn(f0);
            __nv_bfloat16 h1 = __float2bfloat16_rn(f1);
            __nv_bfloat16 l0 = __float2bfloat16_rn(f0 - __bfloat162float(h0));
            __nv_bfloat16 l1 = __float2bfloat16_rn(f1 - __bfloat162float(h1));
            ah[k >> 1] = (uint32_t)__bfloat16_as_ushort(h1) << 16 | __bfloat16_as_ushort(h0);
            al[k >> 1] = (uint32_t)__bfloat16_as_ushort(l1) << 16 | __bfloat16_as_ushort(l0);
        }
    }
    __syncthreads();

    // ---- mainloop: warp (mw, nw) computes m32 x n32 ----
    const int wid = tid >> 5, lane = tid & 31;
    const int mw = wid & 3, nw = wid >> 2;
    const int m0 = mw * 32, n0 = nw * 32;

    // fragment lane addressing (verified in R5)
    const int a_row    = m0 + (lane & 15);
    const int a_coloff = (lane >> 4) * 8;
    const int b_row    = n0 + (lane & 7) + ((lane & 16) ? 8 : 0);
    const int b_coloff = ((lane >> 3) & 1) * 8;

    const uint32_t a0b = smem_u32(Ah + a_row * TSTRIDE + a_coloff);
    const uint32_t a1b = a0b + 16 * TSTRIDE * 2;
    const uint32_t b0b = smem_u32(Bh + b_row * TSTRIDE + b_coloff);
    const uint32_t b1b = b0b + 16 * TSTRIDE * 2;

    float4 acc[8];   // [i*4+j]: m16 block i (0..1), n8 block j (0..3)
    #pragma unroll
    for (int i = 0; i < 8; ++i) acc[i] = make_float4(0.f, 0.f, 0.f, 0.f);

    #pragma unroll 2
    for (int ks = 0; ks < 8; ++ks) {
        const uint32_t ko = ks * 32;
        uint32_t ah0, ah1, ah2, ah3, ah4, ah5, ah6, ah7;
        uint32_t al0, al1, al2, al3, al4, al5, al6, al7;
        uint32_t bh0, bh1, bh2, bh3, bh4, bh5, bh6, bh7;
        uint32_t bl0, bl1, bl2, bl3, bl4, bl5, bl6, bl7;
        LDSM_X4(ah0, ah1, ah2, ah3, a0b + ko);
        LDSM_X4(ah4, ah5, ah6, ah7, a1b + ko);
        LDSM_X4(bh0, bh1, bh2, bh3, b0b + ko);
        LDSM_X4(bh4, bh5, bh6, bh7, b1b + ko);
        LDSM_X4(al0, al1, al2, al3, a0b + LO_OFF + ko);
        LDSM_X4(al4, al5, al6, al7, a1b + LO_OFF + ko);
        LDSM_X4(bl0, bl1, bl2, bl3, b0b + LO_OFF + ko);
        LDSM_X4(bl4, bl5, bl6, bl7, b1b + LO_OFF + ko);

        // pass 1: Ah x Bh
        MMA_BF16(acc[0], ah0, ah1, ah2, ah3, bh0, bh1);
        MMA_BF16(acc[1], ah0, ah1, ah2, ah3, bh2, bh3);
        MMA_BF16(acc[2], ah0, ah1, ah2, ah3, bh4, bh5);
        MMA_BF16(acc[3], ah0, ah1, ah2, ah3, bh6, bh7);
        MMA_BF16(acc[4], ah4, ah5, ah6, ah7, bh0, bh1);
        MMA_BF16(acc[5], ah4, ah5, ah6, ah7, bh2, bh3);
        MMA_BF16(acc[6], ah4, ah5, ah6, ah7, bh4, bh5);
        MMA_BF16(acc[7], ah4, ah5, ah6, ah7, bh6, bh7);
        // pass 2: Al x Bh
        MMA_BF16(acc[0], al0, al1, al2, al3, bh0, bh1);
        MMA_BF16(acc[1], al0, al1, al2, al3, bh2, bh3);
        MMA_BF16(acc[2], al0, al1, al2, al3, bh4, bh5);
        MMA_BF16(acc[3], al0, al1, al2, al3, bh6, bh7);
        MMA_BF16(acc[4], al4, al5, al6, al7, bh0, bh1);
        MMA_BF16(acc[5], al4, al5, al6, al7, bh2, bh3);
        MMA_BF16(acc[6], al4, al5, al6, al7, bh4, bh5);
        MMA_BF16(acc[7], al4, al5, al6, al7, bh6, bh7);
        // pass 3: Ah x Bl
        MMA_BF16(acc[0], ah0, ah1, ah2, ah3, bl0, bl1);
        MMA_BF16(acc[1], ah0, ah1, ah2, ah3, bl2, bl3);
        MMA_BF16(acc[2], ah0, ah1, ah2, ah3, bl4, bl5);
        MMA_BF16(acc[3], ah0, ah1, ah2, ah3, bl6, bl7);
        MMA_BF16(acc[4], ah4, ah5, ah6, ah7, bl0, bl1);
        MMA_BF16(acc[5], ah4, ah5, ah6, ah7, bl2, bl3);
        MMA_BF16(acc[6], ah4, ah5, ah6, ah7, bl4, bl5);
        MMA_BF16(acc[7], ah4, ah5, ah6, ah7, bl6, bl7);
    }

    // ---- epilogue: D fragment (g,2q)/(g+8,2q) -> global, + bias (+relu) ----
    {
        const int g  = lane >> 2;
        const int qi = lane & 3;
        #pragma unroll
        for (int i = 0; i < 2; ++i) {
            const int orow0 = row_base + m0 + i * 16 + g;
            const int orow1 = orow0 + 8;
            #pragma unroll
            for (int j = 0; j < 4; ++j) {
                const int col = n0 + j * 8 + qi * 2;
                const float4 a = acc[i * 4 + j];
                float2 bb = *(const float2*)(bias + col);
                float2 v0 = make_float2(a.x + bb.x, a.y + bb.y);
                float2 v1 = make_float2(a.z + bb.x, a.w + bb.y);
                if (FIRST) {
                    v0.x = fmaxf(v0.x, 0.f); v0.y = fmaxf(v0.y, 0.f);
                    v1.x = fmaxf(v1.x, 0.f); v1.y = fmaxf(v1.y, 0.f);
                }
                if (orow0 < N_NODES) *(float2*)(Y + (size_t)orow0 * DIM + col) = v0;
                if (orow1 < N_NODES) *(float2*)(Y + (size_t)orow1 * DIM + col) = v1;
            }
        }
    }

    // ---- first pass also zeroes agg/deg for this block's rows ----
    if (FIRST) {
        #pragma unroll
        for (int it = 0; it < 8; ++it) {
            int idx = tid + it * GTHREADS;          // 0..4095
            int rr = idx >> 5, cc = (idx & 31) * 4;
            int gr = row_base + rr;
            if (gr < N_NODES)
                *(float4*)(g_agg + (size_t)gr * DIM + cc) =
                    make_float4(0.f, 0.f, 0.f, 0.f);
        }
        if (tid < 128) {
            int gr = row_base + tid;
            if (gr < N_NODES) g_deg[gr] = 0.f;
        }
    }
}

// ---------------------------------------------------------------------------
// Scatter: one warp per edge, red.global.add.v4.f32 (no-return reduction).
// ---------------------------------------------------------------------------
__global__ void __launch_bounds__(256)
scatter_kernel(const void* __restrict__ eiv)
{
    int e    = (blockIdx.x * blockDim.x + threadIdx.x) >> 5;
    int lane = threadIdx.x & 31;
    if (e >= N_EDGES) return;

    long long s, d;
    if (g_is64) {
        const long long* ei = (const long long*)eiv;
        s = __ldg(ei + e);
        d = __ldg(ei + N_EDGES + e);
    } else {
        const int* ei = (const int*)eiv;
        s = __ldg(ei + e);
        d = __ldg(ei + N_EDGES + e);
    }
    if ((unsigned long long)s >= N_NODES || (unsigned long long)d >= N_NODES)
        return;

    float4 v = *(const float4*)(g_h + (size_t)s * DIM + lane * 4);
    float* dst = g_agg + (size_t)d * DIM + lane * 4;
    asm volatile("red.global.add.v4.f32 [%0], {%1,%2,%3,%4};"
                 :: "l"(dst), "f"(v.x), "f"(v.y), "f"(v.z), "f"(v.w)
                 : "memory");
    if (lane == 0) atomicAdd(g_deg + d, 1.0f);
}

// ---------------------------------------------------------------------------
extern "C" void kernel_launch(void* const* d_in, const int* in_sizes, int n_in,
                              void* d_out, int out_size)
{
    const float* x  = (const float*)d_in[0];
    const void*  ei = d_in[1];
    const float* W1 = (const float*)d_in[2];
    const float* b1 = (const float*)d_in[3];
    const float* W2 = (const float*)d_in[4];
    const float* b2 = (const float*)d_in[5];
    float*       out = (float*)d_out;

    cudaFuncSetAttribute(gemm_mma_kernel<true>,
                         cudaFuncAttributeMaxDynamicSharedMemorySize, SMEM_SZ);
    cudaFuncSetAttribute(gemm_mma_kernel<false>,
                         cudaFuncAttributeMaxDynamicSharedMemorySize, SMEM_SZ);

    // 0) edge dtype detect
    detect_kernel<<<1, 1>>>(ei);
    // 1) h = relu(x W1^T + b1); zero agg/deg
    gemm_mma_kernel<true><<<GBLOCKS, GTHREADS, SMEM_SZ>>>(x, W1, b1, nullptr);
    // 2) agg[dst] += h[src]; deg[dst] += 1
    scatter_kernel<<<(N_EDGES * 32 + 255) / 256, 256>>>(ei);
    // 3) out = (agg/deg + h) W2^T + b2
    gemm_mma_kernel<false><<<GBLOCKS, GTHREADS, SMEM_SZ>>>(nullptr, W2, b2, out);
}

// round 12
// speedup vs baseline: 2.8814x; 2.8814x over previous
#include <cuda_runtime.h>
#include <cuda_bf16.h>
#include <cstdint>

#define N_NODES 50000
#define N_EDGES 400000
#define DIM     128
#define GTHREADS 512
#define GBLOCKS  ((N_NODES + 127) / 128)     // 391

#define TSTRIDE 136                          // bf16/row: 272B = 4-bank shift, LDSM conflict-free
#define TILE_ELEMS (128 * TSTRIDE)
#define LO_OFF (TILE_ELEMS * 2)              // byte offset hi-tile -> lo-tile
#define SMEM_SZ (4 * TILE_ELEMS * 2)         // Ah, Al, Bh, Bl  = 139264 B

// ---- scratch (no allocations allowed) ----
__device__ float g_h  [(size_t)N_NODES * DIM];
__device__ float g_agg[(size_t)N_NODES * DIM];
__device__ float g_deg[N_NODES];
__device__ int   g_is64;
// W hi/lo images in the exact padded smem tile layout: [layer][hi|lo]
__device__ __nv_bfloat16 g_wimg[2][2 * TILE_ELEMS];

// ---------------------------------------------------------------------------
__device__ __forceinline__ uint32_t smem_u32(const void* p) {
    uint32_t a;
    asm("{ .reg .u64 t; cvta.to.shared.u64 t, %1; cvt.u32.u64 %0, t; }"
        : "=r"(a) : "l"(p));
    return a;
}

#define LDSM_X4(r0, r1, r2, r3, a)                                             \
    asm volatile("ldmatrix.sync.aligned.m8n8.x4.shared.b16 {%0,%1,%2,%3}, [%4];" \
                 : "=r"(r0), "=r"(r1), "=r"(r2), "=r"(r3) : "r"(a))

#define MMA_BF16(d, a0, a1, a2, a3, b0, b1)                                    \
    asm volatile("mma.sync.aligned.m16n8k16.row.col.f32.bf16.bf16.f32 "        \
                 "{%0,%1,%2,%3}, {%4,%5,%6,%7}, {%8,%9}, {%0,%1,%2,%3};"       \
                 : "+f"((d).x), "+f"((d).y), "+f"((d).z), "+f"((d).w)          \
                 : "r"(a0), "r"(a1), "r"(a2), "r"(a3), "r"(b0), "r"(b1))

__device__ __forceinline__ void split2(float f0, float f1, uint32_t& hp, uint32_t& lp) {
    __nv_bfloat16 h0 = __float2bfloat16_rn(f0);
    __nv_bfloat16 h1 = __float2bfloat16_rn(f1);
    __nv_bfloat16 l0 = __float2bfloat16_rn(f0 - __bfloat162float(h0));
    __nv_bfloat16 l1 = __float2bfloat16_rn(f1 - __bfloat162float(h1));
    hp = (uint32_t)__bfloat16_as_ushort(h1) << 16 | __bfloat16_as_ushort(h0);
    lp = (uint32_t)__bfloat16_as_ushort(l1) << 16 | __bfloat16_as_ushort(l0);
}

// ---------------------------------------------------------------------------
// detect edge_index dtype (JAX may downcast int64 -> int32)
// ---------------------------------------------------------------------------
__global__ void detect_kernel(const void* eiv) {
    const long long* p = (const long long*)eiv;
    int ok64 = 1;
    for (int i = 0; i < 64; ++i) {
        long long v = p[i];
        if (v < 0 || v >= N_NODES) { ok64 = 0; break; }
    }
    g_is64 = ok64;
}

// ---------------------------------------------------------------------------
// Prep: convert W (fp32 [128][128]) -> hi/lo bf16 images in padded tile layout.
// blockIdx.y = layer. Thread handles 2 consecutive k (one uint32 per tile).
// ---------------------------------------------------------------------------
__global__ void prep_w_kernel(const float* __restrict__ W1,
                              const float* __restrict__ W2)
{
    const float* W = blockIdx.y ? W2 : W1;
    __nv_bfloat16* img = g_wimg[blockIdx.y];
    int idx = blockIdx.x * blockDim.x + threadIdx.x;   // 0..8191
    if (idx >= DIM * DIM / 2) return;
    int c = idx >> 6;           // row 0..127
    int k = (idx & 63) * 2;     // col 0..126
    float f0 = W[c * DIM + k], f1 = W[c * DIM + k + 1];
    uint32_t hp, lp;
    split2(f0, f1, hp, lp);
    *(uint32_t*)&img[c * TSTRIDE + k]              = hp;
    *(uint32_t*)&img[TILE_ELEMS + c * TSTRIDE + k] = lp;
}

// ---------------------------------------------------------------------------
// Tensor-core GEMM tile (mma.sync bf16, fp32 acc):
//   Y[128,128] = act( Z[128,128] @ W^T + b )
// fp32 emulated: Z W^T ~= Zh Wh + Zh Wl + Zl Wh  (shared k-step fragments)
// 16 warps in a 4x4 grid; warp = m32 x n32 -> 8 float4 accumulators.
// ---------------------------------------------------------------------------
template<bool FIRST>
__global__ void __launch_bounds__(GTHREADS, 1)
gemm_mma_kernel(const float* __restrict__ Zext,
                const float* __restrict__ Wimg,   // g_wimg[layer]
                const float* __restrict__ bias,
                float* __restrict__ Yext)
{
    extern __shared__ __align__(16) __nv_bfloat16 smem[];
    __nv_bfloat16* Ah = smem;                       // [+TILE_ELEMS] = Al
    __nv_bfloat16* Bh = smem + 2 * TILE_ELEMS;      // [+TILE_ELEMS] = Bl

    const float* Z = FIRST ? Zext : g_h;
    float*       Y = FIRST ? g_h  : Yext;
    const int tid = threadIdx.x;
    const int wid = tid >> 5, lane = tid & 31;
    const int row_base = blockIdx.x * 128;

    // ---- B tiles: straight coalesced copy of the preconverted image ----
    {
        const uint4* src = (const uint4*)Wimg;
        uint4* dst = (uint4*)Bh;
        #pragma unroll
        for (int i = tid; i < 2 * TILE_ELEMS * 2 / 16; i += GTHREADS)
            dst[i] = src[i];
    }

    // ---- A tiles: warp w fills rows 8w..8w+7, lane l covers cols 4l..4l+3 ----
    {
        uint32_t* ahp = (uint32_t*)Ah;
        uint32_t* alp = (uint32_t*)(Ah + TILE_ELEMS);
        #pragma unroll
        for (int rr = 0; rr < 8; ++rr) {
            const int r  = wid * 8 + rr;
            const int gr = row_base + r;
            float4 v = make_float4(0.f, 0.f, 0.f, 0.f);
            if (gr < N_NODES) {
                v = *(const float4*)(Z + (size_t)gr * DIM + lane * 4);
                if (!FIRST) {
                    float dg = (lane == 0) ? g_deg[gr] : 0.f;
                    float inv = 1.0f / fmaxf(__shfl_sync(0xFFFFFFFFu, dg, 0), 1.0f);
                    float4 a = *(const float4*)(g_agg + (size_t)gr * DIM + lane * 4);
                    v.x += a.x * inv; v.y += a.y * inv;
                    v.z += a.z * inv; v.w += a.w * inv;
                }
            }
            uint32_t h0, l0, h1, l1;
            split2(v.x, v.y, h0, l0);
            split2(v.z, v.w, h1, l1);
            const int wo = (r * TSTRIDE + lane * 4) >> 1;   // uint32 index
            ahp[wo] = h0; ahp[wo + 1] = h1;
            alp[wo] = l0; alp[wo + 1] = l1;
        }
    }
    __syncthreads();

    // ---- mainloop: warp (mw, nw) computes m32 x n32 ----
    const int mw = wid & 3, nw = wid >> 2;
    const int m0 = mw * 32, n0 = nw * 32;

    // fragment lane addressing (verified R5/R8)
    const int a_row    = m0 + (lane & 15);
    const int a_coloff = (lane >> 4) * 8;
    const int b_row    = n0 + (lane & 7) + ((lane & 16) ? 8 : 0);
    const int b_coloff = ((lane >> 3) & 1) * 8;

    const uint32_t a0b = smem_u32(Ah + a_row * TSTRIDE + a_coloff);
    const uint32_t a1b = a0b + 16 * TSTRIDE * 2;
    const uint32_t b0b = smem_u32(Bh + b_row * TSTRIDE + b_coloff);
    const uint32_t b1b = b0b + 16 * TSTRIDE * 2;

    float4 acc[8];   // [i*4+j]: m16 block i (0..1), n8 block j (0..3)
    #pragma unroll
    for (int i = 0; i < 8; ++i) acc[i] = make_float4(0.f, 0.f, 0.f, 0.f);

    #pragma unroll 2
    for (int ks = 0; ks < 8; ++ks) {
        const uint32_t ko = ks * 32;
        uint32_t ah0, ah1, ah2, ah3, ah4, ah5, ah6, ah7;
        uint32_t al0, al1, al2, al3, al4, al5, al6, al7;
        uint32_t bh0, bh1, bh2, bh3, bh4, bh5, bh6, bh7;
        uint32_t bl0, bl1, bl2, bl3, bl4, bl5, bl6, bl7;
        LDSM_X4(ah0, ah1, ah2, ah3, a0b + ko);
        LDSM_X4(ah4, ah5, ah6, ah7, a1b + ko);
        LDSM_X4(bh0, bh1, bh2, bh3, b0b + ko);
        LDSM_X4(bh4, bh5, bh6, bh7, b1b + ko);
        LDSM_X4(al0, al1, al2, al3, a0b + LO_OFF + ko);
        LDSM_X4(al4, al5, al6, al7, a1b + LO_OFF + ko);
        LDSM_X4(bl0, bl1, bl2, bl3, b0b + LO_OFF + ko);
        LDSM_X4(bl4, bl5, bl6, bl7, b1b + LO_OFF + ko);

        // pass 1: Ah x Bh
        MMA_BF16(acc[0], ah0, ah1, ah2, ah3, bh0, bh1);
        MMA_BF16(acc[1], ah0, ah1, ah2, ah3, bh2, bh3);
        MMA_BF16(acc[2], ah0, ah1, ah2, ah3, bh4, bh5);
        MMA_BF16(acc[3], ah0, ah1, ah2, ah3, bh6, bh7);
        MMA_BF16(acc[4], ah4, ah5, ah6, ah7, bh0, bh1);
        MMA_BF16(acc[5], ah4, ah5, ah6, ah7, bh2, bh3);
        MMA_BF16(acc[6], ah4, ah5, ah6, ah7, bh4, bh5);
        MMA_BF16(acc[7], ah4, ah5, ah6, ah7, bh6, bh7);
        // pass 2: Al x Bh
        MMA_BF16(acc[0], al0, al1, al2, al3, bh0, bh1);
        MMA_BF16(acc[1], al0, al1, al2, al3, bh2, bh3);
        MMA_BF16(acc[2], al0, al1, al2, al3, bh4, bh5);
        MMA_BF16(acc[3], al0, al1, al2, al3, bh6, bh7);
        MMA_BF16(acc[4], al4, al5, al6, al7, bh0, bh1);
        MMA_BF16(acc[5], al4, al5, al6, al7, bh2, bh3);
        MMA_BF16(acc[6], al4, al5, al6, al7, bh4, bh5);
        MMA_BF16(acc[7], al4, al5, al6, al7, bh6, bh7);
        // pass 3: Ah x Bl
        MMA_BF16(acc[0], ah0, ah1, ah2, ah3, bl0, bl1);
        MMA_BF16(acc[1], ah0, ah1, ah2, ah3, bl2, bl3);
        MMA_BF16(acc[2], ah0, ah1, ah2, ah3, bl4, bl5);
        MMA_BF16(acc[3], ah0, ah1, ah2, ah3, bl6, bl7);
        MMA_BF16(acc[4], ah4, ah5, ah6, ah7, bl0, bl1);
        MMA_BF16(acc[5], ah4, ah5, ah6, ah7, bl2, bl3);
        MMA_BF16(acc[6], ah4, ah5, ah6, ah7, bl4, bl5);
        MMA_BF16(acc[7], ah4, ah5, ah6, ah7, bl6, bl7);
    }

    // ---- epilogue: D fragment (g,2q)/(g+8,2q) -> global, + bias (+relu) ----
    {
        const int g  = lane >> 2;
        const int qi = lane & 3;
        #pragma unroll
        for (int i = 0; i < 2; ++i) {
            const int orow0 = row_base + m0 + i * 16 + g;
            const int orow1 = orow0 + 8;
            #pragma unroll
            for (int j = 0; j < 4; ++j) {
                const int col = n0 + j * 8 + qi * 2;
                const float4 a = acc[i * 4 + j];
                float2 bb = *(const float2*)(bias + col);
                float2 v0 = make_float2(a.x + bb.x, a.y + bb.y);
                float2 v1 = make_float2(a.z + bb.x, a.w + bb.y);
                if (FIRST) {
                    v0.x = fmaxf(v0.x, 0.f); v0.y = fmaxf(v0.y, 0.f);
                    v1.x = fmaxf(v1.x, 0.f); v1.y = fmaxf(v1.y, 0.f);
                }
                if (orow0 < N_NODES) *(float2*)(Y + (size_t)orow0 * DIM + col) = v0;
                if (orow1 < N_NODES) *(float2*)(Y + (size_t)orow1 * DIM + col) = v1;
            }
        }
    }

    // ---- first pass also zeroes agg/deg for this block's rows ----
    if (FIRST) {
        #pragma unroll
        for (int it = 0; it < 8; ++it) {
            int idx = tid + it * GTHREADS;          // 0..4095
            int rr = idx >> 5, cc = (idx & 31) * 4;
            int gr = row_base + rr;
            if (gr < N_NODES)
                *(float4*)(g_agg + (size_t)gr * DIM + cc) =
                    make_float4(0.f, 0.f, 0.f, 0.f);
        }
        if (tid < 128) {
            int gr = row_base + tid;
            if (gr < N_NODES) g_deg[gr] = 0.f;
        }
    }
}

// ---------------------------------------------------------------------------
// Scatter: one warp per edge, red.global.add.v4.f32 (no-return reduction).
// ---------------------------------------------------------------------------
__global__ void __launch_bounds__(256)
scatter_kernel(const void* __restrict__ eiv)
{
    int e    = (blockIdx.x * blockDim.x + threadIdx.x) >> 5;
    int lane = threadIdx.x & 31;
    if (e >= N_EDGES) return;

    long long s, d;
    if (g_is64) {
        const long long* ei = (const long long*)eiv;
        s = __ldg(ei + e);
        d = __ldg(ei + N_EDGES + e);
    } else {
        const int* ei = (const int*)eiv;
        s = __ldg(ei + e);
        d = __ldg(ei + N_EDGES + e);
    }
    if ((unsigned long long)s >= N_NODES || (unsigned long long)d >= N_NODES)
        return;

    float4 v = *(const float4*)(g_h + (size_t)s * DIM + lane * 4);
    float* dst = g_agg + (size_t)d * DIM + lane * 4;
    asm volatile("red.global.add.v4.f32 [%0], {%1,%2,%3,%4};"
                 :: "l"(dst), "f"(v.x), "f"(v.y), "f"(v.z), "f"(v.w)
                 : "memory");
    if (lane == 0) atomicAdd(g_deg + d, 1.0f);
}

// ---------------------------------------------------------------------------
extern "C" void kernel_launch(void* const* d_in, const int* in_sizes, int n_in,
                              void* d_out, int out_size)
{
    const float* x  = (const float*)d_in[0];
    const void*  ei = d_in[1];
    const float* W1 = (const float*)d_in[2];
    const float* b1 = (const float*)d_in[3];
    const float* W2 = (const float*)d_in[4];
    const float* b2 = (const float*)d_in[5];
    float*       out = (float*)d_out;

    cudaFuncSetAttribute(gemm_mma_kernel<true>,
                         cudaFuncAttributeMaxDynamicSharedMemorySize, SMEM_SZ);
    cudaFuncSetAttribute(gemm_mma_kernel<false>,
                         cudaFuncAttributeMaxDynamicSharedMemorySize, SMEM_SZ);

    // device-symbol addresses for the W images (host can't deref __device__ vars)
    __nv_bfloat16* wimg_d = nullptr;
    cudaGetSymbolAddress((void**)&wimg_d, g_wimg);
    const float* wimg0 = (const float*)wimg_d;
    const float* wimg1 = (const float*)(wimg_d + 2 * TILE_ELEMS);

    // 0) edge dtype detect + W hi/lo image prep
    detect_kernel<<<1, 1>>>(ei);
    {
        dim3 g((DIM * DIM / 2 + 255) / 256, 2);
        prep_w_kernel<<<g, 256>>>(W1, W2);
    }
    // 1) h = relu(x W1^T + b1); zero agg/deg
    gemm_mma_kernel<true><<<GBLOCKS, GTHREADS, SMEM_SZ>>>(x, wimg0, b1, nullptr);
    // 2) agg[dst] += h[src]; deg[dst] += 1
    scatter_kernel<<<(N_EDGES * 32 + 255) / 256, 256>>>(ei);
    // 3) out = (agg/deg + h) W2^T + b2
    gemm_mma_kernel<false><<<GBLOCKS, GTHREADS, SMEM_SZ>>>(nullptr, wimg1, b2, out);
}